// round 1
// baseline (speedup 1.0000x reference)
#include <cuda_runtime.h>

#define NBR     4
#define RDIM    1024
#define FDIM    128
#define NDATA   100000
#define KTOT    4097
#define BATCHN  128
#define PER     (BATCHN*KTOT)          /* 524416 */
#define INV_T   14.285714285714286f    /* 1/0.07 */
#define C1      (0.04096f + 1e-7f)
#define LOGC0   (-3.1951593f)          /* ln(0.04096) */

// ---------------- device scratch (static allocs only) ----------------
__device__ float  g_hpart[8*4*BATCHN*FDIM];      // 2 MB  : k-split GEMM partials
__device__ float4 g_e4[4*BATCHN*(FDIM/4)];       // 256 KB: normalized embeddings
__device__ float  g_scr[16*PER];                 // 33.6 MB: unnormalized exp scores
__device__ float  g_zsum[16];                    // per-(i,j) exp sums

// ---------------- K0: zero accumulators + output ----------------
__global__ void k0_zero(float* out) {
    int t = threadIdx.x;
    if (t < 16) g_zsum[t] = 0.f;
    if (t == 0) out[0] = 0.f;
}

// ---------------- K1: partial GEMM  h_part[ks,r,b,d] ----------------
// grid (8 tiles, 8 ksplits, 4 r), 256 threads. Tile 32b x 64d, BK=32.
__global__ __launch_bounds__(256)
void k1_gemm(const float* __restrict__ e0, const float* __restrict__ e1,
             const float* __restrict__ e2, const float* __restrict__ e3,
             const float* __restrict__ W) {
    const int tile = blockIdx.x, ks = blockIdx.y, r = blockIdx.z;
    const float* emb = (r==0)?e0:(r==1)?e1:(r==2)?e2:e3;
    const int b0 = (tile & 3)*32, d0 = (tile>>2)*64;
    __shared__ float As[32][33];
    __shared__ float Bs[64][33];
    const int tid = threadIdx.x;
    const int tb = tid>>5, td = tid&31;
    float acc[4][2] = {};
    for (int kt = 0; kt < 4; kt++) {
        const int k0 = ks*128 + kt*32;
#pragma unroll
        for (int l = 0; l < 4; l++) {
            int lin = tid + l*256;
            As[lin>>5][lin&31] = emb[(b0+(lin>>5))*RDIM + k0 + (lin&31)];
        }
#pragma unroll
        for (int l = 0; l < 8; l++) {
            int lin = tid + l*256;
            Bs[lin>>5][lin&31] = W[r*FDIM*RDIM + (d0+(lin>>5))*RDIM + k0 + (lin&31)];
        }
        __syncthreads();
#pragma unroll
        for (int kk = 0; kk < 32; kk++) {
            float a0=As[tb*4+0][kk], a1=As[tb*4+1][kk], a2=As[tb*4+2][kk], a3=As[tb*4+3][kk];
            float w0=Bs[td*2+0][kk], w1=Bs[td*2+1][kk];
            acc[0][0]=fmaf(a0,w0,acc[0][0]); acc[0][1]=fmaf(a0,w1,acc[0][1]);
            acc[1][0]=fmaf(a1,w0,acc[1][0]); acc[1][1]=fmaf(a1,w1,acc[1][1]);
            acc[2][0]=fmaf(a2,w0,acc[2][0]); acc[2][1]=fmaf(a2,w1,acc[2][1]);
            acc[3][0]=fmaf(a3,w0,acc[3][0]); acc[3][1]=fmaf(a3,w1,acc[3][1]);
        }
        __syncthreads();
    }
#pragma unroll
    for (int bb=0; bb<4; bb++)
#pragma unroll
        for (int dd=0; dd<2; dd++)
            g_hpart[((ks*4+r)*BATCHN + b0+tb*4+bb)*FDIM + d0+td*2+dd] = acc[bb][dd];
}

// ---------------- K2: reduce partials + bias + L2-normalize ----------------
// grid (4, 128), 128 threads (one per d)
__global__ void k2_norm(const float* __restrict__ bias) {
    const int r = blockIdx.x, b = blockIdx.y, d = threadIdx.x;
    float s = bias[r*FDIM + d];
#pragma unroll
    for (int ks = 0; ks < 8; ks++)
        s += g_hpart[((ks*4+r)*BATCHN + b)*FDIM + d];
    float sq = s*s;
#pragma unroll
    for (int o = 16; o; o >>= 1) sq += __shfl_xor_sync(0xffffffffu, sq, o);
    __shared__ float ws[4];
    if ((d & 31) == 0) ws[d>>5] = sq;
    __syncthreads();
    const float tot = ws[0]+ws[1]+ws[2]+ws[3];
    ((float*)g_e4)[(r*BATCHN + b)*FDIM + d] = s * rsqrtf(tot);
}

// ---------------- K3: gather + dots + exp + Z partial sums ----------------
// One kernel instance per branch j (keeps the 51 MB memory[j] footprint
// L2-resident). grid (2 ksplits, 128 b), 256 threads, 4 rows/thread.
#define DOT4(acc, e, m) acc = fmaf((e).x,(m).x, fmaf((e).y,(m).y, fmaf((e).z,(m).z, fmaf((e).w,(m).w, acc))))

template<int J>
__global__ __launch_bounds__(256)
void k3_scores(const float4* __restrict__ mem4, const int* __restrict__ cidx) {
    constexpr int I0 = (J==0)?1:0;
    constexpr int I1 = (J<=1)?2:1;
    constexpr int I2 = (J==3)?2:3;
    const int ksb = blockIdx.x;
    const int b   = blockIdx.y;
    const int tid = threadIdx.x;
    __shared__ float4 es[4][32];
    if (tid < 128) {
        int i = tid >> 5, c = tid & 31;
        es[i][c] = g_e4[(i*BATCHN + b)*32 + c];
    }
    __syncthreads();
    const int  cbase = b*KTOT;
    const long jbase = (long)J*NDATA;
    const int  sb0 = (I0*4+J)*PER + cbase;
    const int  sb1 = (I1*4+J)*PER + cbase;
    const int  sb2 = (I2*4+J)*PER + cbase;
    float zA=0.f, zB=0.f, zC=0.f;
#pragma unroll 1
    for (int iter = 0; iter < 2; iter++) {
        const int k = 1 + ksb*2048 + iter*1024 + tid*4;
        const int n0 = cidx[cbase+k+0], n1 = cidx[cbase+k+1];
        const int n2 = cidx[cbase+k+2], n3 = cidx[cbase+k+3];
        const float4* r0 = mem4 + (jbase + n0)*32;
        const float4* r1 = mem4 + (jbase + n1)*32;
        const float4* r2 = mem4 + (jbase + n2)*32;
        const float4* r3 = mem4 + (jbase + n3)*32;
        float4 aA = {0,0,0,0}, aB = {0,0,0,0}, aC = {0,0,0,0};
#pragma unroll 4
        for (int c = 0; c < 32; c++) {
            float4 m0 = r0[c], m1 = r1[c], m2 = r2[c], m3 = r3[c];
            float4 eA = es[I0][c], eB = es[I1][c], eC = es[I2][c];
            DOT4(aA.x, eA, m0); DOT4(aA.y, eA, m1); DOT4(aA.z, eA, m2); DOT4(aA.w, eA, m3);
            DOT4(aB.x, eB, m0); DOT4(aB.y, eB, m1); DOT4(aB.z, eB, m2); DOT4(aB.w, eB, m3);
            DOT4(aC.x, eC, m0); DOT4(aC.y, eC, m1); DOT4(aC.z, eC, m2); DOT4(aC.w, eC, m3);
        }
        float v;
        v = __expf(aA.x*INV_T); g_scr[sb0+k+0] = v; zA += v;
        v = __expf(aA.y*INV_T); g_scr[sb0+k+1] = v; zA += v;
        v = __expf(aA.z*INV_T); g_scr[sb0+k+2] = v; zA += v;
        v = __expf(aA.w*INV_T); g_scr[sb0+k+3] = v; zA += v;
        v = __expf(aB.x*INV_T); g_scr[sb1+k+0] = v; zB += v;
        v = __expf(aB.y*INV_T); g_scr[sb1+k+1] = v; zB += v;
        v = __expf(aB.z*INV_T); g_scr[sb1+k+2] = v; zB += v;
        v = __expf(aB.w*INV_T); g_scr[sb1+k+3] = v; zB += v;
        v = __expf(aC.x*INV_T); g_scr[sb2+k+0] = v; zC += v;
        v = __expf(aC.y*INV_T); g_scr[sb2+k+1] = v; zC += v;
        v = __expf(aC.z*INV_T); g_scr[sb2+k+2] = v; zC += v;
        v = __expf(aC.w*INV_T); g_scr[sb2+k+3] = v; zC += v;
    }
    // positive sample (k == 0): one warp handles it in the ksb==0 block
    if (ksb == 0 && tid < 32) {
        const int n = cidx[cbase];
        const float4 m = (mem4 + (jbase + n)*32)[tid];
        const float4 eA = es[I0][tid], eB = es[I1][tid], eC = es[I2][tid];
        float pA = m.x*eA.x + m.y*eA.y + m.z*eA.z + m.w*eA.w;
        float pB = m.x*eB.x + m.y*eB.y + m.z*eB.z + m.w*eB.w;
        float pC = m.x*eC.x + m.y*eC.y + m.z*eC.z + m.w*eC.w;
#pragma unroll
        for (int o = 16; o; o >>= 1) {
            pA += __shfl_down_sync(0xffffffffu, pA, o);
            pB += __shfl_down_sync(0xffffffffu, pB, o);
            pC += __shfl_down_sync(0xffffffffu, pC, o);
        }
        if (tid == 0) {
            float v;
            v = __expf(pA*INV_T); g_scr[sb0] = v; atomicAdd(&g_zsum[I0*4+J], v);
            v = __expf(pB*INV_T); g_scr[sb1] = v; atomicAdd(&g_zsum[I1*4+J], v);
            v = __expf(pC*INV_T); g_scr[sb2] = v; atomicAdd(&g_zsum[I2*4+J], v);
        }
    }
    // block-reduce Z partials (3 values)
    __shared__ float ws[3][8];
    float zz[3] = {zA, zB, zC};
#pragma unroll
    for (int t = 0; t < 3; t++) {
        float v = zz[t];
#pragma unroll
        for (int o = 16; o; o >>= 1) v += __shfl_down_sync(0xffffffffu, v, o);
        if ((tid & 31) == 0) ws[t][tid>>5] = v;
    }
    __syncthreads();
    if (tid == 0) {
        const int ii[3] = {I0, I1, I2};
#pragma unroll
        for (int t = 0; t < 3; t++) {
            float s = 0.f;
#pragma unroll
            for (int w = 0; w < 8; w++) s += ws[t][w];
            atomicAdd(&g_zsum[ii[t]*4+J], s);
        }
    }
}

// ---------------- K4: normalize by Z, log terms, final reduction ----------------
// grid (128, 12 pairs), 256 threads. All elements get LOGC0 - log(v+C1);
// the 128 positive entries (k==0) get corrected by (+log(v) - LOGC0).
__global__ __launch_bounds__(256)
void k4_loss(float* out) {
    const int p12 = blockIdx.y;
    const int i = p12/3, jo = p12 - i*3;
    const int j = jo + (jo >= i ? 1 : 0);
    const int pair = i*4 + j;
    __shared__ float sInvZ;
    if (threadIdx.x == 0) {
        float Z = g_zsum[pair] * ((float)NDATA / (float)PER);
        sInvZ = 1.0f / Z;
    }
    __syncthreads();
    const float invZ = sInvZ;
    const int base = pair*PER;
    float lsum = 0.f;
    for (int idx = blockIdx.x*blockDim.x + threadIdx.x; idx < PER; idx += gridDim.x*blockDim.x) {
        float v = g_scr[base+idx]*invZ;
        lsum += LOGC0 - __logf(v + C1);
    }
    if (blockIdx.x == 0 && threadIdx.x < BATCHN) {
        float v = g_scr[base + threadIdx.x*KTOT]*invZ;
        lsum += __logf(v) - LOGC0;
    }
    __shared__ float red[8];
    float v = lsum;
#pragma unroll
    for (int o = 16; o; o >>= 1) v += __shfl_down_sync(0xffffffffu, v, o);
    if ((threadIdx.x & 31) == 0) red[threadIdx.x>>5] = v;
    __syncthreads();
    if (threadIdx.x == 0) {
        float s = 0.f;
#pragma unroll
        for (int w = 0; w < 8; w++) s += red[w];
        atomicAdd(out, s * (-1.0f/(float)BATCHN));
    }
}

// ---------------- launch ----------------
extern "C" void kernel_launch(void* const* d_in, const int* in_sizes, int n_in,
                              void* d_out, int out_size) {
    const float* e0   = (const float*)d_in[0];
    const float* e1   = (const float*)d_in[1];
    const float* e2   = (const float*)d_in[2];
    const float* e3   = (const float*)d_in[3];
    const float* W    = (const float*)d_in[4];
    const float* bias = (const float*)d_in[5];
    const float4* mem = (const float4*)d_in[6];
    const int* cidx   = (const int*)d_in[8];
    float* out        = (float*)d_out;

    k0_zero<<<1, 32>>>(out);
    k1_gemm<<<dim3(8,8,4), 256>>>(e0, e1, e2, e3, W);
    k2_norm<<<dim3(4,128), 128>>>(bias);
    // one kernel per branch j: keeps memory[j] (51 MB) L2-resident
    k3_scores<0><<<dim3(2,128), 256>>>(mem, cidx);
    k3_scores<1><<<dim3(2,128), 256>>>(mem, cidx);
    k3_scores<2><<<dim3(2,128), 256>>>(mem, cidx);
    k3_scores<3><<<dim3(2,128), 256>>>(mem, cidx);
    k4_loss<<<dim3(128,12), 256>>>(out);
}

// round 2
// speedup vs baseline: 1.3125x; 1.3125x over previous
#include <cuda_runtime.h>

#define NBR     4
#define RDIM    1024
#define FDIM    128
#define NDATA   100000
#define KTOT    4097
#define BATCHN  128
#define PER     (BATCHN*KTOT)          /* 524416 */
#define INV_T   14.285714285714286f    /* 1/0.07 */
#define C1      (0.04096f + 1e-7f)
#define LOGC0   (-3.1951593f)          /* ln(0.04096) */

typedef unsigned long long u64;
typedef longlong2 ll2;

// ---------------- device scratch (static allocs only) ----------------
__device__ float  g_hpart[8*4*BATCHN*FDIM];      // 2 MB  : k-split GEMM partials
__device__ float4 g_e4[4*BATCHN*(FDIM/4)];       // 256 KB: normalized embeddings
__device__ float  g_scr[16*PER];                 // 33.6 MB: unnormalized exp scores
__device__ float  g_zsum[16];                    // per-(i,j) exp sums

// packed f32x2 fma: d = a*b + d (element-wise on two packed fp32)
__device__ __forceinline__ void fma2(u64 &d, u64 a, u64 b) {
    asm("fma.rn.f32x2 %0, %1, %2, %0;" : "+l"(d) : "l"(a), "l"(b));
}
__device__ __forceinline__ float lo_plus_hi(u64 v) {
    float a, b;
    asm("mov.b64 {%0, %1}, %2;" : "=f"(a), "=f"(b) : "l"(v));
    return a + b;
}

// ---------------- K0: zero accumulators + output ----------------
__global__ void k0_zero(float* out) {
    int t = threadIdx.x;
    if (t < 16) g_zsum[t] = 0.f;
    if (t == 0) out[0] = 0.f;
}

// ---------------- K1: partial GEMM  h_part[ks,r,b,d] ----------------
__global__ __launch_bounds__(256)
void k1_gemm(const float* __restrict__ e0, const float* __restrict__ e1,
             const float* __restrict__ e2, const float* __restrict__ e3,
             const float* __restrict__ W) {
    const int tile = blockIdx.x, ks = blockIdx.y, r = blockIdx.z;
    const float* emb = (r==0)?e0:(r==1)?e1:(r==2)?e2:e3;
    const int b0 = (tile & 3)*32, d0 = (tile>>2)*64;
    __shared__ float As[32][33];
    __shared__ float Bs[64][33];
    const int tid = threadIdx.x;
    const int tb = tid>>5, td = tid&31;
    float acc[4][2] = {};
    for (int kt = 0; kt < 4; kt++) {
        const int k0 = ks*128 + kt*32;
#pragma unroll
        for (int l = 0; l < 4; l++) {
            int lin = tid + l*256;
            As[lin>>5][lin&31] = emb[(b0+(lin>>5))*RDIM + k0 + (lin&31)];
        }
#pragma unroll
        for (int l = 0; l < 8; l++) {
            int lin = tid + l*256;
            Bs[lin>>5][lin&31] = W[r*FDIM*RDIM + (d0+(lin>>5))*RDIM + k0 + (lin&31)];
        }
        __syncthreads();
#pragma unroll
        for (int kk = 0; kk < 32; kk++) {
            float a0=As[tb*4+0][kk], a1=As[tb*4+1][kk], a2=As[tb*4+2][kk], a3=As[tb*4+3][kk];
            float w0=Bs[td*2+0][kk], w1=Bs[td*2+1][kk];
            acc[0][0]=fmaf(a0,w0,acc[0][0]); acc[0][1]=fmaf(a0,w1,acc[0][1]);
            acc[1][0]=fmaf(a1,w0,acc[1][0]); acc[1][1]=fmaf(a1,w1,acc[1][1]);
            acc[2][0]=fmaf(a2,w0,acc[2][0]); acc[2][1]=fmaf(a2,w1,acc[2][1]);
            acc[3][0]=fmaf(a3,w0,acc[3][0]); acc[3][1]=fmaf(a3,w1,acc[3][1]);
        }
        __syncthreads();
    }
#pragma unroll
    for (int bb=0; bb<4; bb++)
#pragma unroll
        for (int dd=0; dd<2; dd++)
            g_hpart[((ks*4+r)*BATCHN + b0+tb*4+bb)*FDIM + d0+td*2+dd] = acc[bb][dd];
}

// ---------------- K2: reduce partials + bias + L2-normalize ----------------
__global__ void k2_norm(const float* __restrict__ bias) {
    const int r = blockIdx.x, b = blockIdx.y, d = threadIdx.x;
    float s = bias[r*FDIM + d];
#pragma unroll
    for (int ks = 0; ks < 8; ks++)
        s += g_hpart[((ks*4+r)*BATCHN + b)*FDIM + d];
    float sq = s*s;
#pragma unroll
    for (int o = 16; o; o >>= 1) sq += __shfl_xor_sync(0xffffffffu, sq, o);
    __shared__ float ws[4];
    if ((d & 31) == 0) ws[d>>5] = sq;
    __syncthreads();
    const float tot = ws[0]+ws[1]+ws[2]+ws[3];
    ((float*)g_e4)[(r*BATCHN + b)*FDIM + d] = s * rsqrtf(tot);
}

// ---------------- K3 v2: coalesced gather via smem + packed-f32x2 dots ----------------
// grid (16 kc, 128 b), 256 threads. One kernel per branch j (L2 residency).
// Tile: 64 rows staged in smem; warp loads a whole 512B row per LDG.128 (lane t
// takes float4 t -> coalesced, 4 L1 wavefronts). Row stride 36 float4 makes both
// the STS (lane-major) and LDS (4-threads-per-row, interleaved quarters) patterns
// bank-conflict-free. Compute: thread (r=tid>>2, q=tid&3) owns float4 positions
// {q, q+4, ..., q+28} of row r; 3 dots via fma.rn.f32x2; 2-step shfl reduce over q.
#define RSTR 36

template<int J>
__global__ __launch_bounds__(256)
void k3_scores(const float4* __restrict__ mem4, const int* __restrict__ cidx) {
    constexpr int I0 = (J==0)?1:0;
    constexpr int I1 = (J<=1)?2:1;
    constexpr int I2 = (J==3)?2:3;
    __shared__ ll2 tile[64*RSTR];
    __shared__ ll2 es[3][32];
    const int kcb = blockIdx.x;
    const int b   = blockIdx.y;
    const int tid = threadIdx.x;
    const int lane = tid & 31, w = tid >> 5;
    const int r = tid >> 2, q = tid & 3;

    if (tid < 96) {
        int i = tid >> 5, c = tid & 31;
        int ii = (i==0)?I0:(i==1)?I1:I2;
        es[i][c] = ((const ll2*)g_e4)[(ii*BATCHN + b)*32 + c];
    }
    const int  cbase = b*KTOT;
    const long jbase = (long)J*NDATA;
    const int  sb0 = (I0*4+J)*PER + cbase;
    const int  sb1 = (I1*4+J)*PER + cbase;
    const int  sb2 = (I2*4+J)*PER + cbase;
    float zA=0.f, zB=0.f, zC=0.f;
    __syncthreads();

#pragma unroll 1
    for (int t = 0; t < 4; t++) {
        const int kk0 = 1 + kcb*256 + t*64;
        // ---- load 64 rows, warp-cooperative (coalesced) ----
#pragma unroll
        for (int it = 0; it < 8; it++) {
            const int row = w*8 + it;
            const int n = cidx[cbase + kk0 + row];            // broadcast load
            ((float4*)tile)[row*RSTR + lane] =
                (mem4 + (jbase + n)*32)[lane];                // 512B coalesced
        }
        __syncthreads();
        // ---- quarter-row dots ----
        u64 aA0=0,aA1=0,aB0=0,aB1=0,aC0=0,aC1=0;
#pragma unroll
        for (int s = 0; s < 8; s++) {
            const int c = q + 4*s;
            const ll2 m  = tile[r*RSTR + c];
            const ll2 eA = es[0][c], eB = es[1][c], eC = es[2][c];
            fma2(aA0, (u64)m.x, (u64)eA.x); fma2(aA1, (u64)m.y, (u64)eA.y);
            fma2(aB0, (u64)m.x, (u64)eB.x); fma2(aB1, (u64)m.y, (u64)eB.y);
            fma2(aC0, (u64)m.x, (u64)eC.x); fma2(aC1, (u64)m.y, (u64)eC.y);
        }
        float dA = lo_plus_hi(aA0) + lo_plus_hi(aA1);
        float dB = lo_plus_hi(aB0) + lo_plus_hi(aB1);
        float dC = lo_plus_hi(aC0) + lo_plus_hi(aC1);
        dA += __shfl_xor_sync(0xffffffffu, dA, 1);
        dA += __shfl_xor_sync(0xffffffffu, dA, 2);
        dB += __shfl_xor_sync(0xffffffffu, dB, 1);
        dB += __shfl_xor_sync(0xffffffffu, dB, 2);
        dC += __shfl_xor_sync(0xffffffffu, dC, 1);
        dC += __shfl_xor_sync(0xffffffffu, dC, 2);
        if (q == 0) {
            const int k = kk0 + r;
            float v;
            v = __expf(dA*INV_T); g_scr[sb0+k] = v; zA += v;
            v = __expf(dB*INV_T); g_scr[sb1+k] = v; zB += v;
            v = __expf(dC*INV_T); g_scr[sb2+k] = v; zC += v;
        }
        __syncthreads();
    }

    // ---- positive sample (k==0), handled once per b by the kcb==0 block ----
    if (kcb == 0 && tid < 32) {
        const int n = cidx[cbase];
        const float4 m = (mem4 + (jbase + n)*32)[tid];
        const float4* esf = (const float4*)es;
        const float4 eA = esf[0*32+tid], eB = esf[1*32+tid], eC = esf[2*32+tid];
        float pA = m.x*eA.x + m.y*eA.y + m.z*eA.z + m.w*eA.w;
        float pB = m.x*eB.x + m.y*eB.y + m.z*eB.z + m.w*eB.w;
        float pC = m.x*eC.x + m.y*eC.y + m.z*eC.z + m.w*eC.w;
#pragma unroll
        for (int o = 16; o; o >>= 1) {
            pA += __shfl_down_sync(0xffffffffu, pA, o);
            pB += __shfl_down_sync(0xffffffffu, pB, o);
            pC += __shfl_down_sync(0xffffffffu, pC, o);
        }
        if (tid == 0) {
            float v;
            v = __expf(pA*INV_T); g_scr[sb0] = v; atomicAdd(&g_zsum[I0*4+J], v);
            v = __expf(pB*INV_T); g_scr[sb1] = v; atomicAdd(&g_zsum[I1*4+J], v);
            v = __expf(pC*INV_T); g_scr[sb2] = v; atomicAdd(&g_zsum[I2*4+J], v);
        }
    }

    // ---- block-reduce Z partials ----
    __shared__ float ws[3][8];
    float zz[3] = {zA, zB, zC};
#pragma unroll
    for (int t2 = 0; t2 < 3; t2++) {
        float v = zz[t2];
#pragma unroll
        for (int o = 16; o; o >>= 1) v += __shfl_down_sync(0xffffffffu, v, o);
        if (lane == 0) ws[t2][w] = v;
    }
    __syncthreads();
    if (tid == 0) {
        const int ii[3] = {I0, I1, I2};
#pragma unroll
        for (int t2 = 0; t2 < 3; t2++) {
            float s = 0.f;
#pragma unroll
            for (int wi = 0; wi < 8; wi++) s += ws[t2][wi];
            atomicAdd(&g_zsum[ii[t2]*4+J], s);
        }
    }
}

// ---------------- K4: normalize by Z, log terms, final reduction ----------------
__global__ __launch_bounds__(256)
void k4_loss(float* out) {
    const int p12 = blockIdx.y;
    const int i = p12/3, jo = p12 - i*3;
    const int j = jo + (jo >= i ? 1 : 0);
    const int pair = i*4 + j;
    __shared__ float sInvZ;
    if (threadIdx.x == 0) {
        float Z = g_zsum[pair] * ((float)NDATA / (float)PER);
        sInvZ = 1.0f / Z;
    }
    __syncthreads();
    const float invZ = sInvZ;
    const int base = pair*PER;
    float lsum = 0.f;
    for (int idx = blockIdx.x*blockDim.x + threadIdx.x; idx < PER; idx += gridDim.x*blockDim.x) {
        float v = g_scr[base+idx]*invZ;
        lsum += LOGC0 - __logf(v + C1);
    }
    if (blockIdx.x == 0 && threadIdx.x < BATCHN) {
        float v = g_scr[base + threadIdx.x*KTOT]*invZ;
        lsum += __logf(v) - LOGC0;
    }
    __shared__ float red[8];
    float v = lsum;
#pragma unroll
    for (int o = 16; o; o >>= 1) v += __shfl_down_sync(0xffffffffu, v, o);
    if ((threadIdx.x & 31) == 0) red[threadIdx.x>>5] = v;
    __syncthreads();
    if (threadIdx.x == 0) {
        float s = 0.f;
#pragma unroll
        for (int w = 0; w < 8; w++) s += red[w];
        atomicAdd(out, s * (-1.0f/(float)BATCHN));
    }
}

// ---------------- launch ----------------
extern "C" void kernel_launch(void* const* d_in, const int* in_sizes, int n_in,
                              void* d_out, int out_size) {
    const float* e0   = (const float*)d_in[0];
    const float* e1   = (const float*)d_in[1];
    const float* e2   = (const float*)d_in[2];
    const float* e3   = (const float*)d_in[3];
    const float* W    = (const float*)d_in[4];
    const float* bias = (const float*)d_in[5];
    const float4* mem = (const float4*)d_in[6];
    const int* cidx   = (const int*)d_in[8];
    float* out        = (float*)d_out;

    k0_zero<<<1, 32>>>(out);
    k1_gemm<<<dim3(8,8,4), 256>>>(e0, e1, e2, e3, W);
    k2_norm<<<dim3(4,128), 128>>>(bias);
    // one kernel per branch j: keeps memory[j] (51 MB) L2-resident
    k3_scores<0><<<dim3(16,128), 256>>>(mem, cidx);
    k3_scores<1><<<dim3(16,128), 256>>>(mem, cidx);
    k3_scores<2><<<dim3(16,128), 256>>>(mem, cidx);
    k3_scores<3><<<dim3(16,128), 256>>>(mem, cidx);
    k4_loss<<<dim3(128,12), 256>>>(out);
}

// round 3
// speedup vs baseline: 1.8973x; 1.4455x over previous
#include <cuda_runtime.h>

#define NBR     4
#define RDIM    1024
#define FDIM    128
#define NDATA   100000
#define KTOT    4097
#define BATCHN  128
#define PER     (BATCHN*KTOT)          /* 524416 */
#define INV_T   14.285714285714286f    /* 1/0.07 */
#define C1      (0.04096f + 1e-7f)
#define LOGC0   (-3.1951593f)          /* ln(0.04096) */

typedef unsigned long long u64;
typedef longlong2 ll2;

// ---------------- device scratch (static allocs only) ----------------
__device__ float  g_hpart[8*4*BATCHN*FDIM];      // 2 MB  : k-split GEMM partials
__device__ float4 g_e4[4*BATCHN*(FDIM/4)];       // 256 KB: normalized embeddings
__device__ float  g_scr[16*PER];                 // 33.6 MB: unnormalized exp scores
__device__ float  g_zsum[16];                    // per-(i,j) exp sums

// packed f32x2 fma: d = a*b + d
__device__ __forceinline__ void fma2(u64 &d, u64 a, u64 b) {
    asm("fma.rn.f32x2 %0, %1, %2, %0;" : "+l"(d) : "l"(a), "l"(b));
}
__device__ __forceinline__ float lo_plus_hi(u64 v) {
    float a, b;
    asm("mov.b64 {%0, %1}, %2;" : "=f"(a), "=f"(b) : "l"(v));
    return a + b;
}

// ---------------- K0: zero accumulators + output ----------------
__global__ void k0_zero(float* out) {
    int t = threadIdx.x;
    if (t < 16) g_zsum[t] = 0.f;
    if (t == 0) out[0] = 0.f;
}

// ---------------- K1: partial GEMM  h_part[ks,r,b,d] ----------------
__global__ __launch_bounds__(256)
void k1_gemm(const float* __restrict__ e0, const float* __restrict__ e1,
             const float* __restrict__ e2, const float* __restrict__ e3,
             const float* __restrict__ W) {
    const int tile = blockIdx.x, ks = blockIdx.y, r = blockIdx.z;
    const float* emb = (r==0)?e0:(r==1)?e1:(r==2)?e2:e3;
    const int b0 = (tile & 3)*32, d0 = (tile>>2)*64;
    __shared__ float As[32][33];
    __shared__ float Bs[64][33];
    const int tid = threadIdx.x;
    const int tb = tid>>5, td = tid&31;
    float acc[4][2] = {};
    for (int kt = 0; kt < 4; kt++) {
        const int k0 = ks*128 + kt*32;
#pragma unroll
        for (int l = 0; l < 4; l++) {
            int lin = tid + l*256;
            As[lin>>5][lin&31] = emb[(b0+(lin>>5))*RDIM + k0 + (lin&31)];
        }
#pragma unroll
        for (int l = 0; l < 8; l++) {
            int lin = tid + l*256;
            Bs[lin>>5][lin&31] = W[r*FDIM*RDIM + (d0+(lin>>5))*RDIM + k0 + (lin&31)];
        }
        __syncthreads();
#pragma unroll
        for (int kk = 0; kk < 32; kk++) {
            float a0=As[tb*4+0][kk], a1=As[tb*4+1][kk], a2=As[tb*4+2][kk], a3=As[tb*4+3][kk];
            float w0=Bs[td*2+0][kk], w1=Bs[td*2+1][kk];
            acc[0][0]=fmaf(a0,w0,acc[0][0]); acc[0][1]=fmaf(a0,w1,acc[0][1]);
            acc[1][0]=fmaf(a1,w0,acc[1][0]); acc[1][1]=fmaf(a1,w1,acc[1][1]);
            acc[2][0]=fmaf(a2,w0,acc[2][0]); acc[2][1]=fmaf(a2,w1,acc[2][1]);
            acc[3][0]=fmaf(a3,w0,acc[3][0]); acc[3][1]=fmaf(a3,w1,acc[3][1]);
        }
        __syncthreads();
    }
#pragma unroll
    for (int bb=0; bb<4; bb++)
#pragma unroll
        for (int dd=0; dd<2; dd++)
            g_hpart[((ks*4+r)*BATCHN + b0+tb*4+bb)*FDIM + d0+td*2+dd] = acc[bb][dd];
}

// ---------------- K2: reduce partials + bias + L2-normalize ----------------
__global__ void k2_norm(const float* __restrict__ bias) {
    const int r = blockIdx.x, b = blockIdx.y, d = threadIdx.x;
    float s = bias[r*FDIM + d];
#pragma unroll
    for (int ks = 0; ks < 8; ks++)
        s += g_hpart[((ks*4+r)*BATCHN + b)*FDIM + d];
    float sq = s*s;
#pragma unroll
    for (int o = 16; o; o >>= 1) sq += __shfl_xor_sync(0xffffffffu, sq, o);
    __shared__ float ws[4];
    if ((d & 31) == 0) ws[d>>5] = sq;
    __syncthreads();
    const float tot = ws[0]+ws[1]+ws[2]+ws[3];
    ((float*)g_e4)[(r*BATCHN + b)*FDIM + d] = s * rsqrtf(tot);
}

// ---------------- K3 v3: register-resident e, direct warp gather ----------------
// grid (16 kc, 128 b), 256 threads, one kernel per branch j.
// Lane l covers row (l>>3), segment seg=(l&7). Each LDG.128 loads 4 rows x 128B
// contiguous = 4 lines = 4 wavefronts (optimal). e-vectors (3 branches x 4
// positions seg+8i) live in 48 registers, loaded once. Per-row dot finished by
// 3-step shfl_xor over the 8-lane group. No smem tile at all.
template<int J>
__global__ __launch_bounds__(256)
void k3_scores(const float4* __restrict__ mem4, const int* __restrict__ cidx) {
    constexpr int I0 = (J==0)?1:0;
    constexpr int I1 = (J<=1)?2:1;
    constexpr int I2 = (J==3)?2:3;
    const int kcb = blockIdx.x;
    const int b   = blockIdx.y;
    const int tid = threadIdx.x;
    const int lane = tid & 31, w = tid >> 5;
    const int seg = lane & 7, rg = lane >> 3;

    // ---- e-vectors into registers (one-time) ----
    const ll2* e2p = (const ll2*)g_e4;
    u64 eA[8], eB[8], eC[8];
#pragma unroll
    for (int ii = 0; ii < 4; ii++) {
        ll2 vA = e2p[(I0*BATCHN + b)*32 + seg + 8*ii];
        ll2 vB = e2p[(I1*BATCHN + b)*32 + seg + 8*ii];
        ll2 vC = e2p[(I2*BATCHN + b)*32 + seg + 8*ii];
        eA[2*ii] = (u64)vA.x; eA[2*ii+1] = (u64)vA.y;
        eB[2*ii] = (u64)vB.x; eB[2*ii+1] = (u64)vB.y;
        eC[2*ii] = (u64)vC.x; eC[2*ii+1] = (u64)vC.y;
    }

    const int  cbase = b*KTOT;
    const long jbase = (long)J*NDATA;
    const int  sb0 = (I0*4+J)*PER + cbase;
    const int  sb1 = (I1*4+J)*PER + cbase;
    const int  sb2 = (I2*4+J)*PER + cbase;

    // ---- prefetch this thread's 8 row indices ----
    const int kbase = 1 + kcb*256 + w*4 + rg;
    int nidx[8];
#pragma unroll
    for (int it = 0; it < 8; it++) nidx[it] = cidx[cbase + kbase + it*32];

    float zA = 0.f, zB = 0.f, zC = 0.f;

#pragma unroll 2
    for (int it = 0; it < 8; it++) {
        const ll2* rp = (const ll2*)mem4 + (jbase + nidx[it])*32 + seg;
        const ll2 m0 = rp[0], m1 = rp[8], m2 = rp[16], m3 = rp[24];
        u64 a0=0,a1=0,b0=0,b1=0,c0=0,c1=0;
        fma2(a0,(u64)m0.x,eA[0]); fma2(a1,(u64)m0.y,eA[1]);
        fma2(b0,(u64)m0.x,eB[0]); fma2(b1,(u64)m0.y,eB[1]);
        fma2(c0,(u64)m0.x,eC[0]); fma2(c1,(u64)m0.y,eC[1]);
        fma2(a0,(u64)m1.x,eA[2]); fma2(a1,(u64)m1.y,eA[3]);
        fma2(b0,(u64)m1.x,eB[2]); fma2(b1,(u64)m1.y,eB[3]);
        fma2(c0,(u64)m1.x,eC[2]); fma2(c1,(u64)m1.y,eC[3]);
        fma2(a0,(u64)m2.x,eA[4]); fma2(a1,(u64)m2.y,eA[5]);
        fma2(b0,(u64)m2.x,eB[4]); fma2(b1,(u64)m2.y,eB[5]);
        fma2(c0,(u64)m2.x,eC[4]); fma2(c1,(u64)m2.y,eC[5]);
        fma2(a0,(u64)m3.x,eA[6]); fma2(a1,(u64)m3.y,eA[7]);
        fma2(b0,(u64)m3.x,eB[6]); fma2(b1,(u64)m3.y,eB[7]);
        fma2(c0,(u64)m3.x,eC[6]); fma2(c1,(u64)m3.y,eC[7]);
        float dA = lo_plus_hi(a0) + lo_plus_hi(a1);
        float dB = lo_plus_hi(b0) + lo_plus_hi(b1);
        float dC = lo_plus_hi(c0) + lo_plus_hi(c1);
#pragma unroll
        for (int o = 1; o < 8; o <<= 1) {
            dA += __shfl_xor_sync(0xffffffffu, dA, o);
            dB += __shfl_xor_sync(0xffffffffu, dB, o);
            dC += __shfl_xor_sync(0xffffffffu, dC, o);
        }
        if (seg == 0) {
            const int k = kbase + it*32;
            float v;
            v = __expf(dA*INV_T); g_scr[sb0+k] = v; zA += v;
            v = __expf(dB*INV_T); g_scr[sb1+k] = v; zB += v;
            v = __expf(dC*INV_T); g_scr[sb2+k] = v; zC += v;
        }
    }

    // ---- positive sample (k==0), handled once per b by the kcb==0 block ----
    if (kcb == 0 && tid < 32) {
        const int n = cidx[cbase];
        const float4 m = (mem4 + (jbase + n)*32)[lane];
        const float4 fA = g_e4[(I0*BATCHN + b)*32 + lane];
        const float4 fB = g_e4[(I1*BATCHN + b)*32 + lane];
        const float4 fC = g_e4[(I2*BATCHN + b)*32 + lane];
        float pA = m.x*fA.x + m.y*fA.y + m.z*fA.z + m.w*fA.w;
        float pB = m.x*fB.x + m.y*fB.y + m.z*fB.z + m.w*fB.w;
        float pC = m.x*fC.x + m.y*fC.y + m.z*fC.z + m.w*fC.w;
#pragma unroll
        for (int o = 16; o; o >>= 1) {
            pA += __shfl_down_sync(0xffffffffu, pA, o);
            pB += __shfl_down_sync(0xffffffffu, pB, o);
            pC += __shfl_down_sync(0xffffffffu, pC, o);
        }
        if (tid == 0) {
            float v;
            v = __expf(pA*INV_T); g_scr[sb0] = v; atomicAdd(&g_zsum[I0*4+J], v);
            v = __expf(pB*INV_T); g_scr[sb1] = v; atomicAdd(&g_zsum[I1*4+J], v);
            v = __expf(pC*INV_T); g_scr[sb2] = v; atomicAdd(&g_zsum[I2*4+J], v);
        }
    }

    // ---- block-reduce Z partials ----
    __shared__ float ws[3][8];
    float zz[3] = {zA, zB, zC};
#pragma unroll
    for (int t2 = 0; t2 < 3; t2++) {
        float v = zz[t2];
#pragma unroll
        for (int o = 16; o; o >>= 1) v += __shfl_down_sync(0xffffffffu, v, o);
        if (lane == 0) ws[t2][w] = v;
    }
    __syncthreads();
    if (tid == 0) {
        const int ii[3] = {I0, I1, I2};
#pragma unroll
        for (int t2 = 0; t2 < 3; t2++) {
            float s = 0.f;
#pragma unroll
            for (int wi = 0; wi < 8; wi++) s += ws[t2][wi];
            atomicAdd(&g_zsum[ii[t2]*4+J], s);
        }
    }
}

// ---------------- K4: normalize by Z, log terms, final reduction ----------------
__global__ __launch_bounds__(256)
void k4_loss(float* out) {
    const int p12 = blockIdx.y;
    const int i = p12/3, jo = p12 - i*3;
    const int j = jo + (jo >= i ? 1 : 0);
    const int pair = i*4 + j;
    __shared__ float sInvZ;
    if (threadIdx.x == 0) {
        float Z = g_zsum[pair] * ((float)NDATA / (float)PER);
        sInvZ = 1.0f / Z;
    }
    __syncthreads();
    const float invZ = sInvZ;
    const int base = pair*PER;
    float lsum = 0.f;
    for (int idx = blockIdx.x*blockDim.x + threadIdx.x; idx < PER; idx += gridDim.x*blockDim.x) {
        float v = g_scr[base+idx]*invZ;
        lsum += LOGC0 - __logf(v + C1);
    }
    if (blockIdx.x == 0 && threadIdx.x < BATCHN) {
        float v = g_scr[base + threadIdx.x*KTOT]*invZ;
        lsum += __logf(v) - LOGC0;
    }
    __shared__ float red[8];
    float v = lsum;
#pragma unroll
    for (int o = 16; o; o >>= 1) v += __shfl_down_sync(0xffffffffu, v, o);
    if ((threadIdx.x & 31) == 0) red[threadIdx.x>>5] = v;
    __syncthreads();
    if (threadIdx.x == 0) {
        float s = 0.f;
#pragma unroll
        for (int w = 0; w < 8; w++) s += red[w];
        atomicAdd(out, s * (-1.0f/(float)BATCHN));
    }
}

// ---------------- launch ----------------
extern "C" void kernel_launch(void* const* d_in, const int* in_sizes, int n_in,
                              void* d_out, int out_size) {
    const float* e0   = (const float*)d_in[0];
    const float* e1   = (const float*)d_in[1];
    const float* e2   = (const float*)d_in[2];
    const float* e3   = (const float*)d_in[3];
    const float* W    = (const float*)d_in[4];
    const float* bias = (const float*)d_in[5];
    const float4* mem = (const float4*)d_in[6];
    const int* cidx   = (const int*)d_in[8];
    float* out        = (float*)d_out;

    k0_zero<<<1, 32>>>(out);
    k1_gemm<<<dim3(8,8,4), 256>>>(e0, e1, e2, e3, W);
    k2_norm<<<dim3(4,128), 128>>>(bias);
    // one kernel per branch j: keeps memory[j] (51 MB) L2-resident
    k3_scores<0><<<dim3(16,128), 256>>>(mem, cidx);
    k3_scores<1><<<dim3(16,128), 256>>>(mem, cidx);
    k3_scores<2><<<dim3(16,128), 256>>>(mem, cidx);
    k3_scores<3><<<dim3(16,128), 256>>>(mem, cidx);
    k4_loss<<<dim3(128,12), 256>>>(out);
}

// round 8
// speedup vs baseline: 2.2543x; 1.1882x over previous
#include <cuda_runtime.h>

#define NBR     4
#define RDIM    1024
#define FDIM    128
#define NDATA   100000
#define KTOT    4097
#define BATCHN  128
#define PER     (BATCHN*KTOT)          /* 524416 */
#define INV_T   14.285714285714286f    /* 1/0.07 */
#define C1      (0.04096f + 1e-7f)
#define LOGC0   (-3.1951593f)          /* ln(0.04096) */

typedef unsigned long long u64;
typedef longlong2 ll2;

// ---------------- device scratch (static allocs only) ----------------
__device__ float  g_hpart[8*4*BATCHN*FDIM];      // 2 MB  : k-split GEMM partials
__device__ float4 g_e4[4*BATCHN*(FDIM/4)];       // 256 KB: normalized embeddings
__device__ float  g_scr[16*PER];                 // 33.6 MB: unnormalized exp scores
__device__ float  g_zsum[16];                    // per-(i,j) exp sums

// packed f32x2 fma: d = a*b + d
__device__ __forceinline__ void fma2(u64 &d, u64 a, u64 b) {
    asm("fma.rn.f32x2 %0, %1, %2, %0;" : "+l"(d) : "l"(a), "l"(b));
}
__device__ __forceinline__ float lo_plus_hi(u64 v) {
    float a, b;
    asm("mov.b64 {%0, %1}, %2;" : "=f"(a), "=f"(b) : "l"(v));
    return a + b;
}

// ---------------- K0: zero accumulators + output ----------------
__global__ void k0_zero(float* out) {
    int t = threadIdx.x;
    if (t < 16) g_zsum[t] = 0.f;
    if (t == 0) out[0] = 0.f;
}

// ---------------- K1: partial GEMM  h_part[ks,r,b,d] ----------------
__global__ __launch_bounds__(256)
void k1_gemm(const float* __restrict__ e0, const float* __restrict__ e1,
             const float* __restrict__ e2, const float* __restrict__ e3,
             const float* __restrict__ W) {
    const int tile = blockIdx.x, ks = blockIdx.y, r = blockIdx.z;
    const float* emb = (r==0)?e0:(r==1)?e1:(r==2)?e2:e3;
    const int b0 = (tile & 3)*32, d0 = (tile>>2)*64;
    __shared__ float As[32][33];
    __shared__ float Bs[64][33];
    const int tid = threadIdx.x;
    const int tb = tid>>5, td = tid&31;
    float acc[4][2] = {};
    for (int kt = 0; kt < 4; kt++) {
        const int k0 = ks*128 + kt*32;
#pragma unroll
        for (int l = 0; l < 4; l++) {
            int lin = tid + l*256;
            As[lin>>5][lin&31] = emb[(b0+(lin>>5))*RDIM + k0 + (lin&31)];
        }
#pragma unroll
        for (int l = 0; l < 8; l++) {
            int lin = tid + l*256;
            Bs[lin>>5][lin&31] = W[r*FDIM*RDIM + (d0+(lin>>5))*RDIM + k0 + (lin&31)];
        }
        __syncthreads();
#pragma unroll
        for (int kk = 0; kk < 32; kk++) {
            float a0=As[tb*4+0][kk], a1=As[tb*4+1][kk], a2=As[tb*4+2][kk], a3=As[tb*4+3][kk];
            float w0=Bs[td*2+0][kk], w1=Bs[td*2+1][kk];
            acc[0][0]=fmaf(a0,w0,acc[0][0]); acc[0][1]=fmaf(a0,w1,acc[0][1]);
            acc[1][0]=fmaf(a1,w0,acc[1][0]); acc[1][1]=fmaf(a1,w1,acc[1][1]);
            acc[2][0]=fmaf(a2,w0,acc[2][0]); acc[2][1]=fmaf(a2,w1,acc[2][1]);
            acc[3][0]=fmaf(a3,w0,acc[3][0]); acc[3][1]=fmaf(a3,w1,acc[3][1]);
        }
        __syncthreads();
    }
#pragma unroll
    for (int bb=0; bb<4; bb++)
#pragma unroll
        for (int dd=0; dd<2; dd++)
            g_hpart[((ks*4+r)*BATCHN + b0+tb*4+bb)*FDIM + d0+td*2+dd] = acc[bb][dd];
}

// ---------------- K2: reduce partials + bias + L2-normalize ----------------
__global__ void k2_norm(const float* __restrict__ bias) {
    const int r = blockIdx.x, b = blockIdx.y, d = threadIdx.x;
    float s = bias[r*FDIM + d];
#pragma unroll
    for (int ks = 0; ks < 8; ks++)
        s += g_hpart[((ks*4+r)*BATCHN + b)*FDIM + d];
    float sq = s*s;
#pragma unroll
    for (int o = 16; o; o >>= 1) sq += __shfl_xor_sync(0xffffffffu, sq, o);
    __shared__ float ws[4];
    if ((d & 31) == 0) ws[d>>5] = sq;
    __syncthreads();
    const float tot = ws[0]+ws[1]+ws[2]+ws[3];
    ((float*)g_e4)[(r*BATCHN + b)*FDIM + d] = s * rsqrtf(tot);
}

// ---------------- K3 v4: merged-j, software-pipelined row loads ----------------
// grid (16 kc, 128 b, 4 j), 256 threads. j = blockIdx.z (z slowest in bid
// linearization -> equal-j blocks stay temporally clustered -> per-j L2
// residency preserved, single launch).
// Lane l covers row (l>>3), segment seg=(l&7): warp's LDG.128 touches 4 rows x
// 128B contiguous = 4 lines (optimal). e-vectors in 48 regs. Row loads for
// iteration it+1 are issued immediately after iteration it's FMAs consume
// m0..m3 (in-place rotation, no extra regs) and BEFORE the shfl/exp tail, so
// the ~260cyc L2 latency overlaps the tail.
__global__ __launch_bounds__(256, 3)
void k3_scores(const float4* __restrict__ mem4, const int* __restrict__ cidx) {
    const int j  = blockIdx.z;
    const int i0 = (j==0) ? 1 : 0;
    const int i1 = (j<=1) ? 2 : 1;
    const int i2 = (j==3) ? 2 : 3;
    const int kcb = blockIdx.x;
    const int b   = blockIdx.y;
    const int tid = threadIdx.x;
    const int lane = tid & 31, w = tid >> 5;
    const int seg = lane & 7, rg = lane >> 3;

    // ---- e-vectors into registers (one-time) ----
    const ll2* e2p = (const ll2*)g_e4;
    u64 eA[8], eB[8], eC[8];
#pragma unroll
    for (int ii = 0; ii < 4; ii++) {
        ll2 vA = e2p[(i0*BATCHN + b)*32 + seg + 8*ii];
        ll2 vB = e2p[(i1*BATCHN + b)*32 + seg + 8*ii];
        ll2 vC = e2p[(i2*BATCHN + b)*32 + seg + 8*ii];
        eA[2*ii] = (u64)vA.x; eA[2*ii+1] = (u64)vA.y;
        eB[2*ii] = (u64)vB.x; eB[2*ii+1] = (u64)vB.y;
        eC[2*ii] = (u64)vC.x; eC[2*ii+1] = (u64)vC.y;
    }

    const int  cbase = b*KTOT;
    const int  sb0 = (i0*4+j)*PER + cbase;
    const int  sb1 = (i1*4+j)*PER + cbase;
    const int  sb2 = (i2*4+j)*PER + cbase;
    const ll2* base = (const ll2*)mem4 + (long)j*NDATA*32 + seg;

    // ---- prefetch this thread's 8 row indices ----
    const int kbase = 1 + kcb*256 + w*4 + rg;
    int nidx[8];
#pragma unroll
    for (int it = 0; it < 8; it++) nidx[it] = cidx[cbase + kbase + it*32];

    float zA = 0.f, zB = 0.f, zC = 0.f;

    // ---- preload row 0 ----
    {
        const ll2* rp = base + (long)nidx[0]*32;
        ll2 m0 = rp[0], m1 = rp[8], m2 = rp[16], m3 = rp[24];

#pragma unroll
        for (int it = 0; it < 8; it++) {
            u64 a0=0,a1=0,b0_=0,b1_=0,c0=0,c1=0;
            // chunks 0,1
            fma2(a0,(u64)m0.x,eA[0]); fma2(a1,(u64)m0.y,eA[1]);
            fma2(b0_,(u64)m0.x,eB[0]); fma2(b1_,(u64)m0.y,eB[1]);
            fma2(c0,(u64)m0.x,eC[0]); fma2(c1,(u64)m0.y,eC[1]);
            fma2(a0,(u64)m1.x,eA[2]); fma2(a1,(u64)m1.y,eA[3]);
            fma2(b0_,(u64)m1.x,eB[2]); fma2(b1_,(u64)m1.y,eB[3]);
            fma2(c0,(u64)m1.x,eC[2]); fma2(c1,(u64)m1.y,eC[3]);
            // prefetch next row, first half (in-place)
            const ll2* rq = base + (long)nidx[(it+1) & 7]*32;
            if (it < 7) { m0 = rq[0]; m1 = rq[8]; }
            // chunks 2,3
            fma2(a0,(u64)m2.x,eA[4]); fma2(a1,(u64)m2.y,eA[5]);
            fma2(b0_,(u64)m2.x,eB[4]); fma2(b1_,(u64)m2.y,eB[5]);
            fma2(c0,(u64)m2.x,eC[4]); fma2(c1,(u64)m2.y,eC[5]);
            fma2(a0,(u64)m3.x,eA[6]); fma2(a1,(u64)m3.y,eA[7]);
            fma2(b0_,(u64)m3.x,eB[6]); fma2(b1_,(u64)m3.y,eB[7]);
            fma2(c0,(u64)m3.x,eC[6]); fma2(c1,(u64)m3.y,eC[7]);
            // prefetch next row, second half (in-place)
            if (it < 7) { m2 = rq[16]; m3 = rq[24]; }
            // reduction tail (overlaps in-flight loads)
            float dA = lo_plus_hi(a0) + lo_plus_hi(a1);
            float dB = lo_plus_hi(b0_) + lo_plus_hi(b1_);
            float dC = lo_plus_hi(c0) + lo_plus_hi(c1);
#pragma unroll
            for (int o = 1; o < 8; o <<= 1) {
                dA += __shfl_xor_sync(0xffffffffu, dA, o);
                dB += __shfl_xor_sync(0xffffffffu, dB, o);
                dC += __shfl_xor_sync(0xffffffffu, dC, o);
            }
            if (seg == 0) {
                const int k = kbase + it*32;
                float v;
                v = __expf(dA*INV_T); g_scr[sb0+k] = v; zA += v;
                v = __expf(dB*INV_T); g_scr[sb1+k] = v; zB += v;
                v = __expf(dC*INV_T); g_scr[sb2+k] = v; zC += v;
            }
        }
    }

    // ---- positive sample (k==0), handled once per (b,j) by the kcb==0 block ----
    if (kcb == 0 && tid < 32) {
        const int n = cidx[cbase];
        const float4 m = (mem4 + ((long)j*NDATA + n)*32)[lane];
        const float4 fA = g_e4[(i0*BATCHN + b)*32 + lane];
        const float4 fB = g_e4[(i1*BATCHN + b)*32 + lane];
        const float4 fC = g_e4[(i2*BATCHN + b)*32 + lane];
        float pA = m.x*fA.x + m.y*fA.y + m.z*fA.z + m.w*fA.w;
        float pB = m.x*fB.x + m.y*fB.y + m.z*fB.z + m.w*fB.w;
        float pC = m.x*fC.x + m.y*fC.y + m.z*fC.z + m.w*fC.w;
#pragma unroll
        for (int o = 16; o; o >>= 1) {
            pA += __shfl_down_sync(0xffffffffu, pA, o);
            pB += __shfl_down_sync(0xffffffffu, pB, o);
            pC += __shfl_down_sync(0xffffffffu, pC, o);
        }
        if (tid == 0) {
            float v;
            v = __expf(pA*INV_T); g_scr[sb0] = v; atomicAdd(&g_zsum[i0*4+j], v);
            v = __expf(pB*INV_T); g_scr[sb1] = v; atomicAdd(&g_zsum[i1*4+j], v);
            v = __expf(pC*INV_T); g_scr[sb2] = v; atomicAdd(&g_zsum[i2*4+j], v);
        }
    }

    // ---- block-reduce Z partials ----
    __shared__ float ws[3][8];
    float zz[3] = {zA, zB, zC};
#pragma unroll
    for (int t2 = 0; t2 < 3; t2++) {
        float v = zz[t2];
#pragma unroll
        for (int o = 16; o; o >>= 1) v += __shfl_down_sync(0xffffffffu, v, o);
        if (lane == 0) ws[t2][w] = v;
    }
    __syncthreads();
    if (tid == 0) {
        const int ii[3] = {i0, i1, i2};
#pragma unroll
        for (int t2 = 0; t2 < 3; t2++) {
            float s = 0.f;
#pragma unroll
            for (int wi = 0; wi < 8; wi++) s += ws[t2][wi];
            atomicAdd(&g_zsum[ii[t2]*4+j], s);
        }
    }
}

// ---------------- K4: normalize by Z, log terms, final reduction ----------------
__global__ __launch_bounds__(256)
void k4_loss(float* out) {
    const int p12 = blockIdx.y;
    const int i = p12/3, jo = p12 - i*3;
    const int j = jo + (jo >= i ? 1 : 0);
    const int pair = i*4 + j;
    __shared__ float sInvZ;
    if (threadIdx.x == 0) {
        float Z = g_zsum[pair] * ((float)NDATA / (float)PER);
        sInvZ = 1.0f / Z;
    }
    __syncthreads();
    const float invZ = sInvZ;
    const int base = pair*PER;
    float lsum = 0.f;
    for (int idx = blockIdx.x*blockDim.x + threadIdx.x; idx < PER; idx += gridDim.x*blockDim.x) {
        float v = g_scr[base+idx]*invZ;
        lsum += LOGC0 - __logf(v + C1);
    }
    if (blockIdx.x == 0 && threadIdx.x < BATCHN) {
        float v = g_scr[base + threadIdx.x*KTOT]*invZ;
        lsum += __logf(v) - LOGC0;
    }
    __shared__ float red[8];
    float v = lsum;
#pragma unroll
    for (int o = 16; o; o >>= 1) v += __shfl_down_sync(0xffffffffu, v, o);
    if ((threadIdx.x & 31) == 0) red[threadIdx.x>>5] = v;
    __syncthreads();
    if (threadIdx.x == 0) {
        float s = 0.f;
#pragma unroll
        for (int w = 0; w < 8; w++) s += red[w];
        atomicAdd(out, s * (-1.0f/(float)BATCHN));
    }
}

// ---------------- launch ----------------
extern "C" void kernel_launch(void* const* d_in, const int* in_sizes, int n_in,
                              void* d_out, int out_size) {
    const float* e0   = (const float*)d_in[0];
    const float* e1   = (const float*)d_in[1];
    const float* e2   = (const float*)d_in[2];
    const float* e3   = (const float*)d_in[3];
    const float* W    = (const float*)d_in[4];
    const float* bias = (const float*)d_in[5];
    const float4* mem = (const float4*)d_in[6];
    const int* cidx   = (const int*)d_in[8];
    float* out        = (float*)d_out;

    k0_zero<<<1, 32>>>(out);
    k1_gemm<<<dim3(8,8,4), 256>>>(e0, e1, e2, e3, W);
    k2_norm<<<dim3(4,128), 128>>>(bias);
    k3_scores<<<dim3(16,128,4), 256>>>(mem, cidx);   // j = blockIdx.z (clustered)
    k4_loss<<<dim3(128,12), 256>>>(out);
}